// round 5
// baseline (speedup 1.0000x reference)
#include <cuda_runtime.h>
#include <math.h>

#define NE 3
#define BB 8
#define TT 1024
#define HH 128
#define EE 64
#define LL 3
#define DI 256
#define SN 16
#define KC 4
#define RR 8
#define MM (BB*TT)         // 8192 rows per encoder
#define EPSF 1e-7f

// ---------------- scratch (no allocations allowed) ----------------
__device__ float g_h0[NE*MM*HH];
__device__ float g_h1[NE*MM*HH];
__device__ float g_xz[NE*MM*2*DI];
__device__ float g_xc[NE*MM*DI];
__device__ float g_xdbl[NE*MM*40];
__device__ float g_dt[NE*MM*DI];
__device__ float g_y[NE*MM*DI];

__device__ __forceinline__ float siluf(float v) { return v / (1.f + __expf(-v)); }

// ---------------- embed: h = x * w + b ----------------
__global__ void k_embed(const float* __restrict__ x, const float* __restrict__ w,
                        const float* __restrict__ b) {
    int idx = blockIdx.x * blockDim.x + threadIdx.x;
    if (idx >= NE*MM*HH) return;
    int hh  = idx % HH;
    int row = (idx / HH) % MM;
    int ne  = idx / (HH*MM);
    g_h0[idx] = x[ne*MM + row] * w[ne*HH + hh] + b[ne*HH + hh];
}

// ================= BIG SGEMM: 128x128 tile, 8x8 microtile, double-buffered =========
// C[m][n] = sum_k A[m][k] * W[n][k];  M%128==0, Nn%128==0, Kk%16==0
__global__ void __launch_bounds__(256) sgemm_big(
    const float* __restrict__ A, const float* __restrict__ W,
    float* __restrict__ C, int Nn, int Kk, int sA, int sW, int sC)
{
    __shared__ float As[2][16][132];
    __shared__ float Bs[2][16][132];

    int ne = blockIdx.z;
    A += ne * sA; W += ne * sW; C += ne * sC;
    int m0 = blockIdx.x * 128, n0 = blockIdx.y * 128;
    int tid = threadIdx.x;
    int tx = tid & 15, ty = tid >> 4;

    // load mapping: row = tid&127, khalf = tid>>7 (k offset 0 or 8)
    int lr = tid & 127;
    int lk = (tid >> 7) * 8;

    const float* ap = A + (m0 + lr) * Kk + lk;
    const float* wp = W + (n0 + lr) * Kk + lk;

    float acc[8][8];
#pragma unroll
    for (int i = 0; i < 8; i++)
#pragma unroll
        for (int j = 0; j < 8; j++) acc[i][j] = 0.f;

    // preload tile 0
    float4 av0 = *(const float4*)(ap + 0);
    float4 av1 = *(const float4*)(ap + 4);
    float4 wv0 = *(const float4*)(wp + 0);
    float4 wv1 = *(const float4*)(wp + 4);
    As[0][lk+0][lr] = av0.x; As[0][lk+1][lr] = av0.y; As[0][lk+2][lr] = av0.z; As[0][lk+3][lr] = av0.w;
    As[0][lk+4][lr] = av1.x; As[0][lk+5][lr] = av1.y; As[0][lk+6][lr] = av1.z; As[0][lk+7][lr] = av1.w;
    Bs[0][lk+0][lr] = wv0.x; Bs[0][lk+1][lr] = wv0.y; Bs[0][lk+2][lr] = wv0.z; Bs[0][lk+3][lr] = wv0.w;
    Bs[0][lk+4][lr] = wv1.x; Bs[0][lk+5][lr] = wv1.y; Bs[0][lk+6][lr] = wv1.z; Bs[0][lk+7][lr] = wv1.w;
    __syncthreads();

    int s = 0;
    for (int k0 = 0; k0 < Kk; k0 += 16) {
        bool more = (k0 + 16) < Kk;
        if (more) {
            av0 = *(const float4*)(ap + k0 + 16);
            av1 = *(const float4*)(ap + k0 + 20);
            wv0 = *(const float4*)(wp + k0 + 16);
            wv1 = *(const float4*)(wp + k0 + 20);
        }
#pragma unroll
        for (int k = 0; k < 16; k++) {
            float4 a0 = *(const float4*)&As[s][k][ty*8];
            float4 a1 = *(const float4*)&As[s][k][ty*8+4];
            float4 b0 = *(const float4*)&Bs[s][k][tx*8];
            float4 b1 = *(const float4*)&Bs[s][k][tx*8+4];
            float a[8] = {a0.x,a0.y,a0.z,a0.w,a1.x,a1.y,a1.z,a1.w};
            float b[8] = {b0.x,b0.y,b0.z,b0.w,b1.x,b1.y,b1.z,b1.w};
#pragma unroll
            for (int i = 0; i < 8; i++)
#pragma unroll
                for (int j = 0; j < 8; j++) acc[i][j] = fmaf(a[i], b[j], acc[i][j]);
        }
        if (more) {
            int ns = s ^ 1;
            As[ns][lk+0][lr] = av0.x; As[ns][lk+1][lr] = av0.y; As[ns][lk+2][lr] = av0.z; As[ns][lk+3][lr] = av0.w;
            As[ns][lk+4][lr] = av1.x; As[ns][lk+5][lr] = av1.y; As[ns][lk+6][lr] = av1.z; As[ns][lk+7][lr] = av1.w;
            Bs[ns][lk+0][lr] = wv0.x; Bs[ns][lk+1][lr] = wv0.y; Bs[ns][lk+2][lr] = wv0.z; Bs[ns][lk+3][lr] = wv0.w;
            Bs[ns][lk+4][lr] = wv1.x; Bs[ns][lk+5][lr] = wv1.y; Bs[ns][lk+6][lr] = wv1.z; Bs[ns][lk+7][lr] = wv1.w;
            __syncthreads();
            s = ns;
        }
    }

#pragma unroll
    for (int i = 0; i < 8; i++) {
        int m = m0 + ty*8 + i;
        float4 v0 = make_float4(acc[i][0], acc[i][1], acc[i][2], acc[i][3]);
        float4 v1 = make_float4(acc[i][4], acc[i][5], acc[i][6], acc[i][7]);
        *(float4*)(C + m * Nn + n0 + tx*8)     = v0;
        *(float4*)(C + m * Nn + n0 + tx*8 + 4) = v1;
    }
}

// ---------------- small SGEMM (N<=64): 128x64 tile, 8x4 microtile ----------------
// epi==1: C = tanh(C + bias[n])
// epi==2: also compute dt = softplus(C[:, 0:8] @ dw^T + db) into dtout (xdbl path)
__global__ void __launch_bounds__(256) sgemm(
    const float* __restrict__ A, const float* __restrict__ W,
    const float* __restrict__ bias, float* __restrict__ C,
    int Nn, int Kk, int sA, int sW, int sC, int sBias, int epi, int Nvalid,
    const float* __restrict__ dw, const float* __restrict__ db,
    float* __restrict__ dtout)
{
    __shared__ float As[16][132];   // [k][m]
    __shared__ float Bs[16][68];    // [k][n]
    __shared__ float xs[128][9];    // epi==2 staging of x_dbl[:, 0:8]

    int ne = blockIdx.z;
    A += ne * sA; W += ne * sW; C += ne * sC;
    int m0 = blockIdx.x * 128, n0 = blockIdx.y * 64;
    int tid = threadIdx.x;
    int tx = tid & 15, ty = tid >> 4;

    float acc[8][4];
#pragma unroll
    for (int i = 0; i < 8; i++)
#pragma unroll
        for (int j = 0; j < 4; j++) acc[i][j] = 0.f;

    int am = tid >> 2;
    int akq = tid & 3;
    int wn = tid >> 2;
    bool wok = (n0 + wn) < Nvalid;

    for (int k0 = 0; k0 < Kk; k0 += 16) {
#pragma unroll
        for (int q = 0; q < 2; q++) {
            int m = am + q * 64;
            float4 v = *(const float4*)(A + (m0 + m) * Kk + k0 + akq * 4);
            As[akq*4+0][m] = v.x; As[akq*4+1][m] = v.y;
            As[akq*4+2][m] = v.z; As[akq*4+3][m] = v.w;
        }
        {
            float4 v = wok ? *(const float4*)(W + (n0 + wn) * Kk + k0 + akq * 4)
                           : make_float4(0.f, 0.f, 0.f, 0.f);
            Bs[akq*4+0][wn] = v.x; Bs[akq*4+1][wn] = v.y;
            Bs[akq*4+2][wn] = v.z; Bs[akq*4+3][wn] = v.w;
        }
        __syncthreads();
#pragma unroll
        for (int k = 0; k < 16; k++) {
            float4 a0 = *(const float4*)&As[k][ty*8];
            float4 a1 = *(const float4*)&As[k][ty*8+4];
            float4 b  = *(const float4*)&Bs[k][tx*4];
            float a[8] = {a0.x,a0.y,a0.z,a0.w,a1.x,a1.y,a1.z,a1.w};
            float bb[4] = {b.x,b.y,b.z,b.w};
#pragma unroll
            for (int i = 0; i < 8; i++)
#pragma unroll
                for (int j = 0; j < 4; j++) acc[i][j] = fmaf(a[i], bb[j], acc[i][j]);
        }
        __syncthreads();
    }

    if (n0 + tx*4 < Nvalid) {
#pragma unroll
        for (int i = 0; i < 8; i++) {
            int m = m0 + ty*8 + i;
            float4 v = make_float4(acc[i][0], acc[i][1], acc[i][2], acc[i][3]);
            if (epi == 1) {
                v.x = tanhf(v.x + bias[ne*sBias + n0 + tx*4 + 0]);
                v.y = tanhf(v.y + bias[ne*sBias + n0 + tx*4 + 1]);
                v.z = tanhf(v.z + bias[ne*sBias + n0 + tx*4 + 2]);
                v.w = tanhf(v.w + bias[ne*sBias + n0 + tx*4 + 3]);
            }
            *(float4*)(C + m * Nn + n0 + tx*4) = v;
        }
    }

    if (epi == 2) {
        if (tx < 2) {
#pragma unroll
            for (int i = 0; i < 8; i++)
#pragma unroll
                for (int j = 0; j < 4; j++) xs[ty*8+i][tx*4+j] = acc[i][j];
        }
        __syncthreads();
        int d = tid;
        const float* dwp = dw + (ne*LL*DI + d)*RR;
        float wreg[RR];
#pragma unroll
        for (int r = 0; r < RR; r++) wreg[r] = dwp[r];
        float bv = db[ne*LL*DI + d];
        for (int row = 0; row < 128; row++) {
            float s = bv;
#pragma unroll
            for (int r = 0; r < RR; r++) s = fmaf(xs[row][r], wreg[r], s);
            s = (s > 20.f) ? s : log1pf(__expf(s));
            dtout[(ne*MM + m0 + row)*DI + d] = s;
        }
    }
}

// ---------------- depthwise causal conv (K=4) + bias + SiLU ----------------
__global__ void k_conv(const float* __restrict__ cw, const float* __restrict__ cb, int l) {
    int idx = blockIdx.x * blockDim.x + threadIdx.x;  // NE*MM*DI
    if (idx >= NE*MM*DI) return;
    int d   = idx % DI;
    int row = (idx / DI) % MM;
    int ne  = idx / (DI*MM);
    int t = row & (TT - 1);
    int rowbase = row - t;
    const float* w = cw + ((ne*LL + l)*DI + d)*KC;
    float s = cb[(ne*LL + l)*DI + d];
#pragma unroll
    for (int k = 0; k < KC; k++) {
        int tt = t - (KC - 1) + k;
        if (tt >= 0)
            s = fmaf(g_xz[(ne*MM + rowbase + tt)*2*DI + d], w[k], s);
    }
    g_xc[idx] = siluf(s);
}

// ---------------- selective scan: one thread per (ne,b,d,n), 8x unrolled ----------------
__global__ void __launch_bounds__(256) k_scan(
    const float* __restrict__ alog, const float* __restrict__ dvec, int l)
{
    int gid = blockIdx.x * blockDim.x + threadIdx.x;  // NE*BB*DI*SN
    int n  = gid & 15;
    int d  = (gid >> 4) & (DI - 1);
    int b  = (gid >> 12) & (BB - 1);
    int ne = gid >> 15;
    float A  = -__expf(alog[((ne*LL + l)*DI + d)*SN + n]);
    float Dv = dvec[(ne*LL + l)*DI + d];
    int row = (ne*BB + b) * TT;
    const float* __restrict__ pdt = g_dt  + row*DI + d;
    const float* __restrict__ pxc = g_xc  + row*DI + d;
    const float* __restrict__ pxd = g_xdbl + row*40;
    const float* __restrict__ pz  = g_xz  + row*2*DI + DI + d;
    float* __restrict__ py = g_y + row*DI + d;
    float h = 0.f;

    for (int t0 = 0; t0 < TT; t0 += 8) {
        float dtv[8], xcv[8], Bv[8], Cv[8];
#pragma unroll
        for (int u = 0; u < 8; u++) {
            int t = t0 + u;
            dtv[u] = pdt[t*DI];
            xcv[u] = pxc[t*DI];
            Bv[u]  = pxd[t*40 + 8 + n];
            Cv[u]  = pxd[t*40 + 24 + n];
        }
        float dA[8];
#pragma unroll
        for (int u = 0; u < 8; u++) dA[u] = __expf(dtv[u] * A);
        float acc[8];
#pragma unroll
        for (int u = 0; u < 8; u++) {
            h = fmaf(dA[u], h, dtv[u] * Bv[u] * xcv[u]);
            acc[u] = h * Cv[u];
        }
#pragma unroll
        for (int u = 0; u < 8; u++) acc[u] += __shfl_xor_sync(0xffffffffu, acc[u], 8);
#pragma unroll
        for (int u = 0; u < 8; u++) acc[u] += __shfl_xor_sync(0xffffffffu, acc[u], 4);
#pragma unroll
        for (int u = 0; u < 8; u++) acc[u] += __shfl_xor_sync(0xffffffffu, acc[u], 2);
#pragma unroll
        for (int u = 0; u < 8; u++) acc[u] += __shfl_xor_sync(0xffffffffu, acc[u], 1);
        if (n == 0) {
#pragma unroll
            for (int u = 0; u < 8; u++) {
                int t = t0 + u;
                float z = pz[t*2*DI];
                py[t*DI] = (acc[u] + Dv*xcv[u]) * siluf(z);
            }
        }
    }
}

// ---------------- hyperbolic epilogue: one warp per row ----------------
__global__ void __launch_bounds__(256) k_hyper(float* __restrict__ out) {
    int tid  = threadIdx.x;
    int lane = tid & 31;
    int row  = blockIdx.x * 8 + (tid >> 5);
    const int offH  = 3*MM*EE;
    const int offCT = offH + 3*MM*(EE+1);
    const int offCH = offCT + MM*EE;
    float acc0 = 0.f, acc1 = 0.f;

#pragma unroll
    for (int ne = 0; ne < NE; ne++) {
        const float* p = out + ne*MM*EE + row*EE;
        float v0 = p[lane], v1 = p[lane+32];
        float sq = fmaf(v0, v0, v1*v1);
#pragma unroll
        for (int s = 16; s >= 1; s >>= 1) sq += __shfl_xor_sync(0xffffffffu, sq, s);
        float s2 = sq;
        float nn = sqrtf(s2);
        float ns = fmaxf(nn, EPSF);
        float sh = sinhf(ns);
        float scale = sh / ns;
        float s2x = scale*scale*s2;
        float x0 = sqrtf(1.f + s2x);
        float* ph = out + offH + ne*MM*(EE+1) + row*(EE+1);
        if (lane == 0) ph[0] = x0;
        ph[1+lane]    = scale * v0;
        ph[1+lane+32] = scale * v1;
        float nxs = sqrtf(s2x);
        float xm = fmaxf(x0, 1.f + EPSF);
        float dd = logf(xm + sqrtf(fmaxf(xm*xm - 1.f, 0.f)));
        float f = dd / fmaxf(nxs, EPSF) * scale;
        acc0 = fmaf(f, v0, acc0);
        acc1 = fmaf(f, v1, acc1);
    }
    float* pct = out + offCT + row*EE;
    pct[lane]    = acc0;
    pct[lane+32] = acc1;
    float sq = fmaf(acc0, acc0, acc1*acc1);
#pragma unroll
    for (int s = 16; s >= 1; s >>= 1) sq += __shfl_xor_sync(0xffffffffu, sq, s);
    float s2 = sq;
    float nn = sqrtf(s2);
    float ns = fmaxf(nn, EPSF);
    float sh = sinhf(ns);
    float scale = sh / ns;
    float s2x = scale*scale*s2;
    float x0 = sqrtf(1.f + s2x);
    float* pch = out + offCH + row*(EE+1);
    if (lane == 0) pch[0] = x0;
    pch[1+lane]    = scale * acc0;
    pch[1+lane+32] = scale * acc1;
}

// ---------------- launcher ----------------
extern "C" void kernel_launch(void* const* d_in, const int* in_sizes, int n_in,
                              void* d_out, int out_size) {
    const float* x       = (const float*)d_in[0];
    const float* einw    = (const float*)d_in[1];
    const float* einb    = (const float*)d_in[2];
    const float* minw    = (const float*)d_in[3];
    const float* mconvw  = (const float*)d_in[4];
    const float* mconvb  = (const float*)d_in[5];
    const float* mxprojw = (const float*)d_in[6];
    const float* mdtw    = (const float*)d_in[7];
    const float* mdtb    = (const float*)d_in[8];
    const float* malog   = (const float*)d_in[9];
    const float* md      = (const float*)d_in[10];
    const float* moutw   = (const float*)d_in[11];
    const float* eoutw   = (const float*)d_in[12];
    const float* eoutb   = (const float*)d_in[13];
    float* out = (float*)d_out;

    float *h0, *h1, *xz, *xc, *xdbl, *dtb, *yb;
    cudaGetSymbolAddress((void**)&h0,   g_h0);
    cudaGetSymbolAddress((void**)&h1,   g_h1);
    cudaGetSymbolAddress((void**)&xz,   g_xz);
    cudaGetSymbolAddress((void**)&xc,   g_xc);
    cudaGetSymbolAddress((void**)&xdbl, g_xdbl);
    cudaGetSymbolAddress((void**)&dtb,  g_dt);
    cudaGetSymbolAddress((void**)&yb,   g_y);

    k_embed<<<(NE*MM*HH + 255)/256, 256>>>(x, einw, einb);

    float* hcur = h0;
    float* hnxt = h1;
    for (int l = 0; l < LL; l++) {
        // in-proj: (NE x 8192 x 512) = h @ in_w^T  -- big tile kernel
        dim3 g1(MM/128, (2*DI)/128, NE);
        sgemm_big<<<g1, 256>>>(hcur, minw + l*2*DI*HH, xz,
                               2*DI, HH, MM*HH, LL*2*DI*HH, MM*2*DI);
        // conv + silu
        k_conv<<<(NE*MM*DI)/256, 256>>>(mconvw, mconvb, l);
        // x_dbl = xc @ xproj_w^T (N=40 guarded) + fused dt projection
        dim3 gx(MM/128, 1, NE);
        sgemm<<<gx, 256>>>(xc, mxprojw + l*40*DI, nullptr, xdbl,
                           40, DI, MM*DI, LL*40*DI, MM*40, 0, 2, 40,
                           mdtw + l*DI*RR, mdtb + l*DI, dtb);
        // selective scan (fused D-skip + silu(z) gate)
        k_scan<<<(NE*BB*DI*SN)/256, 256>>>(malog, md, l);
        // out-proj: (NE x 8192 x 128) = y @ out_w^T -- big tile kernel
        dim3 g2(MM/128, HH/128, NE);
        sgemm_big<<<g2, 256>>>(yb, moutw + l*HH*DI, hnxt,
                               HH, DI, MM*DI, LL*HH*DI, MM*HH);
        float* tmp = hcur; hcur = hnxt; hnxt = tmp;
    }

    // encoder out-proj with fused bias + tanh -> tangents into d_out
    dim3 g3(MM/128, 1, NE);
    sgemm<<<g3, 256>>>(hcur, eoutw, eoutb, out,
                       EE, HH, MM*HH, EE*HH, MM*EE, EE, 1, EE,
                       nullptr, nullptr, nullptr);

    // hyperbolic maps + combination (one warp per row)
    k_hyper<<<MM/8, 256>>>(out);
}

// round 6
// speedup vs baseline: 1.0320x; 1.0320x over previous
#include <cuda_runtime.h>
#include <math.h>

#define NE 3
#define BB 8
#define TT 1024
#define HH 128
#define EE 64
#define LL 3
#define DI 256
#define SN 16
#define KC 4
#define RR 8
#define MM (BB*TT)         // 8192 rows per encoder
#define EPSF 1e-7f

// ---------------- scratch (no allocations allowed) ----------------
__device__ float g_h0[NE*MM*HH];
__device__ float g_h1[NE*MM*HH];
__device__ float g_xz[NE*MM*2*DI];
__device__ float g_xc[NE*MM*DI];
__device__ float g_xdbl[NE*MM*40];
__device__ float g_dt[NE*MM*DI];
__device__ float g_y[NE*MM*DI];

__device__ __forceinline__ float siluf(float v) { return v / (1.f + __expf(-v)); }

// ---------------- embed: h = x * w + b ----------------
__global__ void k_embed(const float* __restrict__ x, const float* __restrict__ w,
                        const float* __restrict__ b) {
    int idx = blockIdx.x * blockDim.x + threadIdx.x;
    if (idx >= NE*MM*HH) return;
    int hh  = idx % HH;
    int row = (idx / HH) % MM;
    int ne  = idx / (HH*MM);
    g_h0[idx] = x[ne*MM + row] * w[ne*HH + hh] + b[ne*HH + hh];
}

// ======== universal SGEMM: 64x64 tile, BK=16, 4x4 microtile, double-buffered ========
// C[m][n] = sum_k A[m][k] * W[n][k]
// epi==0: plain   epi==1: C = tanh(C + bias[n])
// epi==2: also dt = softplus(C[:, 0:8] @ dw^T + db) into dtout
__global__ void __launch_bounds__(256) sgemm64(
    const float* __restrict__ A, const float* __restrict__ W,
    const float* __restrict__ bias, float* __restrict__ C,
    int Nn, int Kk, int sA, int sW, int sC, int sBias, int epi, int Nvalid,
    const float* __restrict__ dw, const float* __restrict__ db,
    float* __restrict__ dtout)
{
    __shared__ float As[2][16][68];
    __shared__ float Bs[2][16][68];
    __shared__ float xs[64][9];

    int ne = blockIdx.z;
    A += ne * sA; W += ne * sW; C += ne * sC;
    int m0 = blockIdx.x * 64, n0 = blockIdx.y * 64;
    int tid = threadIdx.x;
    int tx = tid & 15, ty = tid >> 4;
    int lr = tid >> 2;             // 0..63 (tile row)
    int kq = (tid & 3) * 4;        // k sub-offset 0,4,8,12

    const float* ap = A + (m0 + lr) * Kk + kq;
    bool wok = (n0 + lr) < Nvalid;
    const float* wp = W + (wok ? (n0 + lr) : 0) * Kk + kq;

    float acc[4][4];
#pragma unroll
    for (int i = 0; i < 4; i++)
#pragma unroll
        for (int j = 0; j < 4; j++) acc[i][j] = 0.f;

    float4 av, wv;
    const float4 fz = make_float4(0.f, 0.f, 0.f, 0.f);

#define STAGE_STORE(buf)                                                     \
    { As[buf][kq+0][lr] = av.x; As[buf][kq+1][lr] = av.y;                    \
      As[buf][kq+2][lr] = av.z; As[buf][kq+3][lr] = av.w;                    \
      Bs[buf][kq+0][lr] = wv.x; Bs[buf][kq+1][lr] = wv.y;                    \
      Bs[buf][kq+2][lr] = wv.z; Bs[buf][kq+3][lr] = wv.w; }

#define STAGE_COMPUTE(buf)                                                   \
    _Pragma("unroll")                                                        \
    for (int k = 0; k < 16; k++) {                                           \
        float4 a = *(const float4*)&As[buf][k][ty*4];                        \
        float4 b = *(const float4*)&Bs[buf][k][tx*4];                        \
        float ar[4] = {a.x, a.y, a.z, a.w};                                  \
        float br[4] = {b.x, b.y, b.z, b.w};                                  \
        _Pragma("unroll")                                                    \
        for (int i = 0; i < 4; i++)                                          \
            _Pragma("unroll")                                                \
            for (int j = 0; j < 4; j++)                                      \
                acc[i][j] = fmaf(ar[i], br[j], acc[i][j]);                   \
    }

    // preload k=0 into buffer 0
    av = *(const float4*)ap;
    wv = wok ? *(const float4*)wp : fz;
    STAGE_STORE(0);
    __syncthreads();

    for (int k0 = 0; k0 < Kk; k0 += 32) {
        bool l1 = (k0 + 16) < Kk;
        if (l1) {
            av = *(const float4*)(ap + k0 + 16);
            wv = wok ? *(const float4*)(wp + k0 + 16) : fz;
        }
        STAGE_COMPUTE(0);
        if (l1) { STAGE_STORE(1); __syncthreads(); }
        bool l2 = (k0 + 32) < Kk;
        if (l2) {
            av = *(const float4*)(ap + k0 + 32);
            wv = wok ? *(const float4*)(wp + k0 + 32) : fz;
        }
        if (l1) STAGE_COMPUTE(1);
        if (l2) { STAGE_STORE(0); __syncthreads(); }
    }

    // epilogue
    if (n0 + tx*4 < Nvalid) {
#pragma unroll
        for (int i = 0; i < 4; i++) {
            int m = m0 + ty*4 + i;
            float4 v = make_float4(acc[i][0], acc[i][1], acc[i][2], acc[i][3]);
            if (epi == 1) {
                v.x = tanhf(v.x + bias[ne*sBias + n0 + tx*4 + 0]);
                v.y = tanhf(v.y + bias[ne*sBias + n0 + tx*4 + 1]);
                v.z = tanhf(v.z + bias[ne*sBias + n0 + tx*4 + 2]);
                v.w = tanhf(v.w + bias[ne*sBias + n0 + tx*4 + 3]);
            }
            *(float4*)(C + m * Nn + n0 + tx*4) = v;
        }
    }

    if (epi == 2) {
        __syncthreads();
        if (tx < 2) {
#pragma unroll
            for (int i = 0; i < 4; i++)
#pragma unroll
                for (int j = 0; j < 4; j++) xs[ty*4+i][tx*4+j] = acc[i][j];
        }
        __syncthreads();
        int d = tid;
        const float* dwp = dw + (ne*LL*DI + d)*RR;
        float wreg[RR];
#pragma unroll
        for (int r = 0; r < RR; r++) wreg[r] = dwp[r];
        float bv = db[ne*LL*DI + d];
#pragma unroll 4
        for (int row = 0; row < 64; row++) {
            float s = bv;
#pragma unroll
            for (int r = 0; r < RR; r++) s = fmaf(xs[row][r], wreg[r], s);
            s = (s > 20.f) ? s : log1pf(__expf(s));
            dtout[(ne*MM + m0 + row)*DI + d] = s;
        }
    }
#undef STAGE_STORE
#undef STAGE_COMPUTE
}

// ---------------- depthwise causal conv (K=4) + bias + SiLU ----------------
__global__ void k_conv(const float* __restrict__ cw, const float* __restrict__ cb, int l) {
    int idx = blockIdx.x * blockDim.x + threadIdx.x;  // NE*MM*DI
    if (idx >= NE*MM*DI) return;
    int d   = idx % DI;
    int row = (idx / DI) % MM;
    int ne  = idx / (DI*MM);
    int t = row & (TT - 1);
    int rowbase = row - t;
    const float* w = cw + ((ne*LL + l)*DI + d)*KC;
    float s = cb[(ne*LL + l)*DI + d];
#pragma unroll
    for (int k = 0; k < KC; k++) {
        int tt = t - (KC - 1) + k;
        if (tt >= 0)
            s = fmaf(g_xz[(ne*MM + rowbase + tt)*2*DI + d], w[k], s);
    }
    g_xc[idx] = siluf(s);
}

// ---------------- selective scan: one thread per (ne,b,d,n), 8x unrolled ----------------
__global__ void __launch_bounds__(256) k_scan(
    const float* __restrict__ alog, const float* __restrict__ dvec, int l)
{
    int gid = blockIdx.x * blockDim.x + threadIdx.x;  // NE*BB*DI*SN
    int n  = gid & 15;
    int d  = (gid >> 4) & (DI - 1);
    int b  = (gid >> 12) & (BB - 1);
    int ne = gid >> 15;
    float A  = -__expf(alog[((ne*LL + l)*DI + d)*SN + n]);
    float Dv = dvec[(ne*LL + l)*DI + d];
    int row = (ne*BB + b) * TT;
    const float* __restrict__ pdt = g_dt  + row*DI + d;
    const float* __restrict__ pxc = g_xc  + row*DI + d;
    const float* __restrict__ pxd = g_xdbl + row*40;
    const float* __restrict__ pz  = g_xz  + row*2*DI + DI + d;
    float* __restrict__ py = g_y + row*DI + d;
    float h = 0.f;

    for (int t0 = 0; t0 < TT; t0 += 8) {
        float dtv[8], xcv[8], Bv[8], Cv[8];
#pragma unroll
        for (int u = 0; u < 8; u++) {
            int t = t0 + u;
            dtv[u] = pdt[t*DI];
            xcv[u] = pxc[t*DI];
            Bv[u]  = pxd[t*40 + 8 + n];
            Cv[u]  = pxd[t*40 + 24 + n];
        }
        float dA[8];
#pragma unroll
        for (int u = 0; u < 8; u++) dA[u] = __expf(dtv[u] * A);
        float acc[8];
#pragma unroll
        for (int u = 0; u < 8; u++) {
            h = fmaf(dA[u], h, dtv[u] * Bv[u] * xcv[u]);
            acc[u] = h * Cv[u];
        }
#pragma unroll
        for (int u = 0; u < 8; u++) acc[u] += __shfl_xor_sync(0xffffffffu, acc[u], 8);
#pragma unroll
        for (int u = 0; u < 8; u++) acc[u] += __shfl_xor_sync(0xffffffffu, acc[u], 4);
#pragma unroll
        for (int u = 0; u < 8; u++) acc[u] += __shfl_xor_sync(0xffffffffu, acc[u], 2);
#pragma unroll
        for (int u = 0; u < 8; u++) acc[u] += __shfl_xor_sync(0xffffffffu, acc[u], 1);
        if (n == 0) {
#pragma unroll
            for (int u = 0; u < 8; u++) {
                int t = t0 + u;
                float z = pz[t*2*DI];
                py[t*DI] = (acc[u] + Dv*xcv[u]) * siluf(z);
            }
        }
    }
}

// ---------------- hyperbolic epilogue: one warp per row ----------------
__global__ void __launch_bounds__(256) k_hyper(float* __restrict__ out) {
    int tid  = threadIdx.x;
    int lane = tid & 31;
    int row  = blockIdx.x * 8 + (tid >> 5);
    const int offH  = 3*MM*EE;
    const int offCT = offH + 3*MM*(EE+1);
    const int offCH = offCT + MM*EE;
    float acc0 = 0.f, acc1 = 0.f;

#pragma unroll
    for (int ne = 0; ne < NE; ne++) {
        const float* p = out + ne*MM*EE + row*EE;
        float v0 = p[lane], v1 = p[lane+32];
        float sq = fmaf(v0, v0, v1*v1);
#pragma unroll
        for (int s = 16; s >= 1; s >>= 1) sq += __shfl_xor_sync(0xffffffffu, sq, s);
        float s2 = sq;
        float nn = sqrtf(s2);
        float ns = fmaxf(nn, EPSF);
        float sh = sinhf(ns);
        float scale = sh / ns;
        float s2x = scale*scale*s2;
        float x0 = sqrtf(1.f + s2x);
        float* ph = out + offH + ne*MM*(EE+1) + row*(EE+1);
        if (lane == 0) ph[0] = x0;
        ph[1+lane]    = scale * v0;
        ph[1+lane+32] = scale * v1;
        float nxs = sqrtf(s2x);
        float xm = fmaxf(x0, 1.f + EPSF);
        float dd = logf(xm + sqrtf(fmaxf(xm*xm - 1.f, 0.f)));
        float f = dd / fmaxf(nxs, EPSF) * scale;
        acc0 = fmaf(f, v0, acc0);
        acc1 = fmaf(f, v1, acc1);
    }
    float* pct = out + offCT + row*EE;
    pct[lane]    = acc0;
    pct[lane+32] = acc1;
    float sq = fmaf(acc0, acc0, acc1*acc1);
#pragma unroll
    for (int s = 16; s >= 1; s >>= 1) sq += __shfl_xor_sync(0xffffffffu, sq, s);
    float s2 = sq;
    float nn = sqrtf(s2);
    float ns = fmaxf(nn, EPSF);
    float sh = sinhf(ns);
    float scale = sh / ns;
    float s2x = scale*scale*s2;
    float x0 = sqrtf(1.f + s2x);
    float* pch = out + offCH + row*(EE+1);
    if (lane == 0) pch[0] = x0;
    pch[1+lane]    = scale * acc0;
    pch[1+lane+32] = scale * acc1;
}

// ---------------- launcher ----------------
extern "C" void kernel_launch(void* const* d_in, const int* in_sizes, int n_in,
                              void* d_out, int out_size) {
    const float* x       = (const float*)d_in[0];
    const float* einw    = (const float*)d_in[1];
    const float* einb    = (const float*)d_in[2];
    const float* minw    = (const float*)d_in[3];
    const float* mconvw  = (const float*)d_in[4];
    const float* mconvb  = (const float*)d_in[5];
    const float* mxprojw = (const float*)d_in[6];
    const float* mdtw    = (const float*)d_in[7];
    const float* mdtb    = (const float*)d_in[8];
    const float* malog   = (const float*)d_in[9];
    const float* md      = (const float*)d_in[10];
    const float* moutw   = (const float*)d_in[11];
    const float* eoutw   = (const float*)d_in[12];
    const float* eoutb   = (const float*)d_in[13];
    float* out = (float*)d_out;

    float *h0, *h1, *xz, *xc, *xdbl, *dtb, *yb;
    cudaGetSymbolAddress((void**)&h0,   g_h0);
    cudaGetSymbolAddress((void**)&h1,   g_h1);
    cudaGetSymbolAddress((void**)&xz,   g_xz);
    cudaGetSymbolAddress((void**)&xc,   g_xc);
    cudaGetSymbolAddress((void**)&xdbl, g_xdbl);
    cudaGetSymbolAddress((void**)&dtb,  g_dt);
    cudaGetSymbolAddress((void**)&yb,   g_y);

    k_embed<<<(NE*MM*HH + 255)/256, 256>>>(x, einw, einb);

    float* hcur = h0;
    float* hnxt = h1;
    for (int l = 0; l < LL; l++) {
        // in-proj: (NE x 8192 x 512) = h @ in_w^T
        dim3 g1(MM/64, (2*DI)/64, NE);
        sgemm64<<<g1, 256>>>(hcur, minw + l*2*DI*HH, nullptr, xz,
                             2*DI, HH, MM*HH, LL*2*DI*HH, MM*2*DI, 0, 0, 2*DI,
                             nullptr, nullptr, nullptr);
        // conv + silu
        k_conv<<<(NE*MM*DI)/256, 256>>>(mconvw, mconvb, l);
        // x_dbl = xc @ xproj_w^T (N=40 guarded) + fused dt projection
        dim3 gx(MM/64, 1, NE);
        sgemm64<<<gx, 256>>>(xc, mxprojw + l*40*DI, nullptr, xdbl,
                             40, DI, MM*DI, LL*40*DI, MM*40, 0, 2, 40,
                             mdtw + l*DI*RR, mdtb + l*DI, dtb);
        // selective scan (fused D-skip + silu(z) gate)
        k_scan<<<(NE*BB*DI*SN)/256, 256>>>(malog, md, l);
        // out-proj: (NE x 8192 x 128) = y @ out_w^T
        dim3 g2(MM/64, HH/64, NE);
        sgemm64<<<g2, 256>>>(yb, moutw + l*HH*DI, nullptr, hnxt,
                             HH, DI, MM*DI, LL*HH*DI, MM*HH, 0, 0, HH,
                             nullptr, nullptr, nullptr);
        float* tmp = hcur; hcur = hnxt; hnxt = tmp;
    }

    // encoder out-proj with fused bias + tanh -> tangents into d_out
    dim3 g3(MM/64, 1, NE);
    sgemm64<<<g3, 256>>>(hcur, eoutw, eoutb, out,
                         EE, HH, MM*HH, EE*HH, MM*EE, EE, 1, EE,
                         nullptr, nullptr, nullptr);

    // hyperbolic maps + combination (one warp per row)
    k_hyper<<<MM/8, 256>>>(out);
}